// round 11
// baseline (speedup 1.0000x reference)
#include <cuda_runtime.h>
#include <cstring>

// Fused JPEG round-trip. Thread owns row r of TWO vertically adjacent 8x8
// blocks; ALL channels packed f32x2 across the tile pair: pY=(Y_A,Y_B),
// pU=(U_A,U_B), pV=(V_A,V_B). Packed quant via magic-number round-half-even.
// Transposes via per-warp conflict-free smem (ull layout).
// Input : d_in[0] = float32 [1,3,2048,2048]; Output: float32 [1,3*2048*2048]

#define IMG_W  2048
#define IMG_H  2048
#define PLANE  (IMG_W * IMG_H)

#define C1 0.4903926402f
#define C2 0.4619397663f
#define C3 0.4157348062f
#define C4 0.3535533906f
#define C5 0.2777851165f
#define C6 0.1913417162f
#define C7 0.0975451610f

__constant__ float cQf[128] = {
    16,11,10,16,24,40,51,61,  12,12,14,19,26,58,60,55,
    14,13,16,24,40,57,69,56,  14,17,22,29,51,87,80,62,
    18,22,37,56,68,109,103,77, 24,35,55,64,81,104,113,92,
    49,64,78,87,103,121,120,101, 72,92,95,98,112,100,103,99,
    17,18,24,47,99,99,99,99,  18,21,26,66,99,99,99,99,
    24,26,56,99,99,99,99,99,  47,66,99,99,99,99,99,99,
    99,99,99,99,99,99,99,99,  99,99,99,99,99,99,99,99,
    99,99,99,99,99,99,99,99,  99,99,99,99,99,99,99,99 };
__constant__ float cRQf[128] = {
    1.f/16,1.f/11,1.f/10,1.f/16,1.f/24,1.f/40,1.f/51,1.f/61,
    1.f/12,1.f/12,1.f/14,1.f/19,1.f/26,1.f/58,1.f/60,1.f/55,
    1.f/14,1.f/13,1.f/16,1.f/24,1.f/40,1.f/57,1.f/69,1.f/56,
    1.f/14,1.f/17,1.f/22,1.f/29,1.f/51,1.f/87,1.f/80,1.f/62,
    1.f/18,1.f/22,1.f/37,1.f/56,1.f/68,1.f/109,1.f/103,1.f/77,
    1.f/24,1.f/35,1.f/55,1.f/64,1.f/81,1.f/104,1.f/113,1.f/92,
    1.f/49,1.f/64,1.f/78,1.f/87,1.f/103,1.f/121,1.f/120,1.f/101,
    1.f/72,1.f/92,1.f/95,1.f/98,1.f/112,1.f/100,1.f/103,1.f/99,
    1.f/17,1.f/18,1.f/24,1.f/47,1.f/99,1.f/99,1.f/99,1.f/99,
    1.f/18,1.f/21,1.f/26,1.f/66,1.f/99,1.f/99,1.f/99,1.f/99,
    1.f/24,1.f/26,1.f/56,1.f/99,1.f/99,1.f/99,1.f/99,1.f/99,
    1.f/47,1.f/66,1.f/99,1.f/99,1.f/99,1.f/99,1.f/99,1.f/99,
    1.f/99,1.f/99,1.f/99,1.f/99,1.f/99,1.f/99,1.f/99,1.f/99,
    1.f/99,1.f/99,1.f/99,1.f/99,1.f/99,1.f/99,1.f/99,1.f/99,
    1.f/99,1.f/99,1.f/99,1.f/99,1.f/99,1.f/99,1.f/99,1.f/99,
    1.f/99,1.f/99,1.f/99,1.f/99,1.f/99,1.f/99,1.f/99,1.f/99 };

// Folded inverse-color + normalization (validated R5-R10)
#define NC_A0 0.0158730159f
#define NC_B0 (-1.93476190e-8f)
#define NC_C0 0.0222539619f
#define NC_K0 (-4.8373935f)
#define NC_A1 0.0161030596f
#define NC_B1 (-0.0055416377f)
#define NC_C1 (-0.0114997768f)
#define NC_K1 0.2006247f
#define NC_A2 0.0149925037f
#define NC_B2 0.0265667181f
#define NC_C2 6.09145427e-9f
#define NC_K2 (-5.1081869f)

#define MAGICF 12582912.0f   // 1.5 * 2^23: (d+M)-M == rint(d) for |d| < 2^22

typedef unsigned long long ull;

__device__ __forceinline__ ull pk(float lo, float hi) {
    float2 t = make_float2(lo, hi); ull r; memcpy(&r, &t, 8); return r;
}
__device__ __forceinline__ ull pk1(float x) { return pk(x, x); }
__device__ __forceinline__ float2 unpk(ull a) {
    float2 t; memcpy(&t, &a, 8); return t;
}
__device__ __forceinline__ ull padd(ull a, ull b) {
    ull r; asm("add.rn.f32x2 %0,%1,%2;" : "=l"(r) : "l"(a), "l"(b)); return r;
}
__device__ __forceinline__ ull pmul(ull a, ull b) {
    ull r; asm("mul.rn.f32x2 %0,%1,%2;" : "=l"(r) : "l"(a), "l"(b)); return r;
}
__device__ __forceinline__ ull pfma(ull a, ull b, ull c) {
    ull r; asm("fma.rn.f32x2 %0,%1,%2,%3;" : "=l"(r) : "l"(a), "l"(b), "l"(c)); return r;
}
__device__ __forceinline__ ull psub(ull a, ull b) { return pfma(b, pk1(-1.0f), a); }

__device__ __forceinline__ void fdct8p(ull v[8]) {
    ull e0=padd(v[0],v[7]), e1=padd(v[1],v[6]), e2=padd(v[2],v[5]), e3=padd(v[3],v[4]);
    ull o0=psub(v[0],v[7]), o1=psub(v[1],v[6]), o2=psub(v[2],v[5]), o3=psub(v[3],v[4]);
    ull s03=padd(e0,e3), s12=padd(e1,e2), d03=psub(e0,e3), d12=psub(e1,e2);
    v[0]=pmul(pk1(C4), padd(s03,s12));
    v[4]=pmul(pk1(C4), psub(s03,s12));
    v[2]=pfma(pk1(C2),d03, pmul(pk1( C6),d12));
    v[6]=pfma(pk1(C6),d03, pmul(pk1(-C2),d12));
    v[1]=pfma(pk1(C1),o0, pfma(pk1( C3),o1, pfma(pk1( C5),o2, pmul(pk1( C7),o3))));
    v[3]=pfma(pk1(C3),o0, pfma(pk1(-C7),o1, pfma(pk1(-C1),o2, pmul(pk1(-C5),o3))));
    v[5]=pfma(pk1(C5),o0, pfma(pk1(-C1),o1, pfma(pk1( C7),o2, pmul(pk1( C3),o3))));
    v[7]=pfma(pk1(C7),o0, pfma(pk1(-C5),o1, pfma(pk1( C3),o2, pmul(pk1(-C1),o3))));
}
__device__ __forceinline__ void idct8p(ull v[8]) {
    ull sp=pmul(pk1(C4), padd(v[0],v[4]));
    ull sm=pmul(pk1(C4), psub(v[0],v[4]));
    ull t1=pfma(pk1(C2),v[2], pmul(pk1( C6),v[6]));
    ull t2=pfma(pk1(C6),v[2], pmul(pk1(-C2),v[6]));
    ull E0=padd(sp,t1), E1=padd(sm,t2), E2=psub(sm,t2), E3=psub(sp,t1);
    ull O0=pfma(pk1(C1),v[1], pfma(pk1( C3),v[3], pfma(pk1( C5),v[5], pmul(pk1( C7),v[7]))));
    ull O1=pfma(pk1(C3),v[1], pfma(pk1(-C7),v[3], pfma(pk1(-C1),v[5], pmul(pk1(-C5),v[7]))));
    ull O2=pfma(pk1(C5),v[1], pfma(pk1(-C1),v[3], pfma(pk1( C7),v[5], pmul(pk1( C3),v[7]))));
    ull O3=pfma(pk1(C7),v[1], pfma(pk1(-C5),v[3], pfma(pk1( C3),v[5], pmul(pk1(-C1),v[7]))));
    v[0]=padd(E0,O0); v[7]=psub(E0,O0);
    v[1]=padd(E1,O1); v[6]=psub(E1,O1);
    v[2]=padd(E2,O2); v[5]=psub(E2,O2);
    v[3]=padd(E3,O3); v[4]=psub(E3,O3);
}

// packed quant/dequant for one channel (8 coefficient pairs)
__device__ __forceinline__ void quantp(ull v[8], const float* qte, int r) {
    const ull MG = pk1(MAGICF);
    #pragma unroll
    for (int i = 0; i < 8; ++i) {
        float2 qq = *(const float2*)(qte + i * 16 + r * 2);
        ull q2  = pk1(qq.x);
        ull rq2 = pk1(qq.y);
        ull nq2 = pk1(-qq.x);
        ull d  = pmul(v[i], rq2);
        ull rn = psub(padd(d, MG), MG);          // round-half-even (== rintf)
        ull e  = pmul(pfma(rn, nq2, v[i]), rq2); // exact residual / q
        v[i]   = pmul(pfma(pmul(e, e), e, rn), q2);
    }
}

// conflict-free ull transpose buffer: row pitch 10, group pitch 84
#define RPU 10
#define GPU 84

__device__ __forceinline__ void writeT(const ull v[8], ull* bg, int r) {
    ull* w = bg + RPU * r;
    #pragma unroll
    for (int k = 0; k < 8; k += 2)
        *(ulonglong2*)(w + k) = make_ulonglong2(v[k], v[k+1]);
}
__device__ __forceinline__ void readT(ull v[8], const ull* bg, int r) {
    #pragma unroll
    for (int k = 0; k < 8; ++k) v[k] = bg[RPU * k + r];
}

__global__ __launch_bounds__(128, 5)
void jpeg_roundtrip_kernel(const float* __restrict__ in, float* __restrict__ out)
{
    // 3 channel buffers x 16 groups x 84 ull = 32256 B
    __shared__ __align__(16) ull tb[3][16 * GPU];
    __shared__ float qt[256];

    const int tid  = threadIdx.x;
    const int warp = tid >> 5;
    const int lane = tid & 31;
    const int r    = lane >> 2;
    const int g    = lane & 3;

    {   // build interleaved quant table (2 entries per thread)
        #pragma unroll
        for (int t = tid; t < 256; t += 128) {
            int w  = t & 1, rr = (t >> 1) & 7, ii = (t >> 4) & 7, ch = t >> 7;
            int si = ch * 64 + ii * 8 + rr;
            qt[t] = w ? cRQf[si] : cQf[si];
        }
    }

    const int grp = warp * 4 + g;
    ull* bgY = tb[0] + grp * GPU;
    ull* bgU = tb[1] + grp * GPU;
    ull* bgV = tb[2] + grp * GPU;

    const int x0    = blockIdx.x * 128 + grp * 8;
    const int yA    = blockIdx.y * 16 + r;
    const int baseA = yA * IMG_W + x0;
    const int baseB = baseA + 8 * IMG_W;

    // ---- issue all 12 loads up front ----
    const float4 ARa = *(const float4*)(in + baseA);
    const float4 ARb = *(const float4*)(in + baseA + 4);
    const float4 AGa = *(const float4*)(in + baseA + PLANE);
    const float4 AGb = *(const float4*)(in + baseA + PLANE + 4);
    const float4 ABa = *(const float4*)(in + baseA + 2*PLANE);
    const float4 ABb = *(const float4*)(in + baseA + 2*PLANE + 4);
    const float4 BRa = *(const float4*)(in + baseB);
    const float4 BRb = *(const float4*)(in + baseB + 4);
    const float4 BGa = *(const float4*)(in + baseB + PLANE);
    const float4 BGb = *(const float4*)(in + baseB + PLANE + 4);
    const float4 BBa = *(const float4*)(in + baseB + 2*PLANE);
    const float4 BBb = *(const float4*)(in + baseB + 2*PLANE + 4);

    __syncthreads();   // quant table ready

    float RA[8] = {ARa.x,ARa.y,ARa.z,ARa.w, ARb.x,ARb.y,ARb.z,ARb.w};
    float GA[8] = {AGa.x,AGa.y,AGa.z,AGa.w, AGb.x,AGb.y,AGb.z,AGb.w};
    float BA[8] = {ABa.x,ABa.y,ABa.z,ABa.w, ABb.x,ABb.y,ABb.z,ABb.w};
    float RB[8] = {BRa.x,BRa.y,BRa.z,BRa.w, BRb.x,BRb.y,BRb.z,BRb.w};
    float GB[8] = {BGa.x,BGa.y,BGa.z,BGa.w, BGb.x,BGb.y,BGb.z,BGb.w};
    float BB[8] = {BBa.x,BBa.y,BBa.z,BBa.w, BBb.x,BBb.y,BBb.z,BBb.w};

    // ---- forward color, packed across tile pair ----
    ull pY[8], pU[8], pV[8];
    #pragma unroll
    for (int k = 0; k < 8; ++k) {
        ull Rp = pk(RA[k], RB[k]);
        ull Gp = pk(GA[k], GB[k]);
        ull Bp = pk(BA[k], BB[k]);
        pY[k] = pfma(Bp, pk1(0.114f), pfma(Gp, pk1(0.587f), pmul(Rp, pk1(0.299f))));
        pU[k] = pfma(Rp, pk1(-0.168736f), pfma(Gp, pk1(-0.331264f), pfma(Bp, pk1(0.5f), pk1(128.0f))));
        pV[k] = pfma(Rp, pk1(0.5f), pfma(Gp, pk1(-0.418688f), pfma(Bp, pk1(-0.081312f), pk1(128.0f))));
    }

    // ---- stage 1: row DCT + transpose ----
    fdct8p(pY); writeT(pY, bgY, r);
    fdct8p(pU); writeT(pU, bgU, r);
    fdct8p(pV); writeT(pV, bgV, r);
    __syncwarp();
    readT(pY, bgY, r);
    readT(pU, bgU, r);
    readT(pV, bgV, r);
    __syncwarp();   // all group lanes' reads done before stage-2 writes

    // ---- stage 2+3: column DCT, quant, column IDCT, transpose back ----
    fdct8p(pY); quantp(pY, qt,       r); idct8p(pY); writeT(pY, bgY, r);
    fdct8p(pU); quantp(pU, qt + 128, r); idct8p(pU); writeT(pU, bgU, r);
    fdct8p(pV); quantp(pV, qt + 128, r); idct8p(pV); writeT(pV, bgV, r);
    __syncwarp();
    readT(pY, bgY, r);
    readT(pU, bgU, r);
    readT(pV, bgV, r);

    // ---- stage 4: row IDCT ----
    idct8p(pY); idct8p(pU); idct8p(pV);

    // ---- folded inverse color + normalize + store (both tiles) ----
    float oRA[8], oGA[8], oBA[8], oRB[8], oGB[8], oBB[8];
    #pragma unroll
    for (int k = 0; k < 8; ++k) {
        ull Rp = pfma(pY[k], pk1(NC_A0), pfma(pU[k], pk1(NC_B0), pfma(pV[k], pk1(NC_C0), pk1(NC_K0))));
        ull Gp = pfma(pY[k], pk1(NC_A1), pfma(pU[k], pk1(NC_B1), pfma(pV[k], pk1(NC_C1), pk1(NC_K1))));
        ull Bp = pfma(pY[k], pk1(NC_A2), pfma(pU[k], pk1(NC_B2), pfma(pV[k], pk1(NC_C2), pk1(NC_K2))));
        float2 rv = unpk(Rp), gv = unpk(Gp), bv = unpk(Bp);
        oRA[k] = rv.x; oRB[k] = rv.y;
        oGA[k] = gv.x; oGB[k] = gv.y;
        oBA[k] = bv.x; oBB[k] = bv.y;
    }
    *(float4*)(out + baseA)               = make_float4(oRA[0],oRA[1],oRA[2],oRA[3]);
    *(float4*)(out + baseA + 4)           = make_float4(oRA[4],oRA[5],oRA[6],oRA[7]);
    *(float4*)(out + baseA + PLANE)       = make_float4(oGA[0],oGA[1],oGA[2],oGA[3]);
    *(float4*)(out + baseA + PLANE + 4)   = make_float4(oGA[4],oGA[5],oGA[6],oGA[7]);
    *(float4*)(out + baseA + 2*PLANE)     = make_float4(oBA[0],oBA[1],oBA[2],oBA[3]);
    *(float4*)(out + baseA + 2*PLANE + 4) = make_float4(oBA[4],oBA[5],oBA[6],oBA[7]);
    *(float4*)(out + baseB)               = make_float4(oRB[0],oRB[1],oRB[2],oRB[3]);
    *(float4*)(out + baseB + 4)           = make_float4(oRB[4],oRB[5],oRB[6],oRB[7]);
    *(float4*)(out + baseB + PLANE)       = make_float4(oGB[0],oGB[1],oGB[2],oGB[3]);
    *(float4*)(out + baseB + PLANE + 4)   = make_float4(oGB[4],oGB[5],oGB[6],oGB[7]);
    *(float4*)(out + baseB + 2*PLANE)     = make_float4(oBB[0],oBB[1],oBB[2],oBB[3]);
    *(float4*)(out + baseB + 2*PLANE + 4) = make_float4(oBB[4],oBB[5],oBB[6],oBB[7]);
}

extern "C" void kernel_launch(void* const* d_in, const int* in_sizes, int n_in,
                              void* d_out, int out_size)
{
    const float* in = (const float*)d_in[0];
    float* out = (float*)d_out;
    dim3 grid(IMG_W / 128, IMG_H / 16);
    jpeg_roundtrip_kernel<<<grid, 128>>>(in, out);
}